// round 3
// baseline (speedup 1.0000x reference)
#include <cuda_runtime.h>
#include <cuda_bf16.h>
#include <math.h>

// ---------------- geometry ----------------
#define NB     2
#define NC     8
#define NV     360
#define ND     512
#define RR     11           // taps
#define HID    176          // hidden channels
#define OC     88           // conv2 out channels = RR*NC
#define NP     (NV*ND)      // 184320 sample columns
#define LL     (NP*RR)      // 2027520
#define NIDX   (128*128*360)// 5898240 indices
#define DT     256          // d-tile per block
#define HCP    88           // hidden channels per phase
#define HP     264          // smem pitch (floats) for x_s / h_s
#define YP     261          // y staging pitch
#define WPITCH 20           // 18 weights + 2 pad (80B rows, 16B aligned)

// scratch (no cudaMalloc allowed)
__device__ float g_A[2u * (unsigned)LL * 8u];        // [b][p][r][c]  ~130MB

// ---------------- f32x2 helpers ----------------
__device__ __forceinline__ void ffma2(unsigned long long& c,
                                      unsigned long long a,
                                      unsigned long long b) {
    asm("fma.rn.f32x2 %0, %1, %2, %0;" : "+l"(c) : "l"(a), "l"(b));
}
__device__ __forceinline__ unsigned long long pack2(float lo, float hi) {
    unsigned long long r;
    asm("mov.b64 %0, {%1, %2};" : "=l"(r) : "f"(lo), "f"(hi));
    return r;
}
__device__ __forceinline__ float2 unpack2(unsigned long long v) {
    float2 f;
    asm("mov.b64 {%0, %1}, %2;" : "=f"(f.x), "=f"(f.y) : "l"(v));
    return f;
}

// ---------------- fused conv1+gelu+conv2, writes A[b][p][r][c] ----------------
__global__ __launch_bounds__(512, 1)
void conv_fused(const float* __restrict__ input,
                const float* __restrict__ w1,
                const float* __restrict__ b1,
                const float* __restrict__ w2,
                const float* __restrict__ b2) {
    extern __shared__ float smem[];
    float* x_s = smem;                       // [8][264]
    float* h_s = smem + 8 * HP;              // [88][264]
    float* w_s = smem + 8 * HP + HCP * HP;   // [16][88][20]

    const int tid  = threadIdx.x;
    const int blk  = blockIdx.x;
    const int bv   = blk >> 1;
    const int tile = blk & 1;
    const int d0   = tile * DT;
    const int b    = bv / NV;
    const int v    = bv - b * NV;

    // ---- load x halo: x_s[ci][j] = input[b,ci,v, d0-2+j], j in [0,260) ----
    for (int i = tid; i < 8 * HP; i += 512) {
        int ci = i / HP, j = i - ci * HP;
        int dG = d0 - 2 + j;
        float val = 0.f;
        if (j < 260 && (unsigned)dG < (unsigned)ND)
            val = input[(((size_t)(b * NC + ci) * NV + v) * ND) + dG];
        x_s[i] = val;
    }

    const int wid   = tid >> 5;
    const int lane  = tid & 31;
    const int c     = wid & 7;       // output channel
    const int rh    = wid >> 3;      // r-half: 0 -> r 0..5, 1 -> r 6..11(pad)
    const int dbase = lane * 8;      // 8 d positions per lane

    // ---- acc init with bias ----
    unsigned long long acc[6][4];
#pragma unroll
    for (int r = 0; r < 6; ++r) {
        int rg = rh * 6 + r;
        float bb = (rg < RR) ? b2[c * RR + rg] : 0.f;
#pragma unroll
        for (int i = 0; i < 4; ++i) acc[r][i] = pack2(bb, bb);
    }

    __syncthreads();

    for (int ph = 0; ph < 2; ++ph) {
        // ---- stage this phase's fc2 weights into smem ----
        // w_s[(c*2+rh)][hcl][rl*3+t] = w2[c*11 + rh*6+rl][ph*88+hcl][t]
        for (int i = tid; i < 16 * HCP * 18; i += 512) {
            int k18 = i % 18;
            int rem = i / 18;            // (c*2+rh)*88 + hcl
            int hcl = rem % HCP;
            int crh = rem / HCP;
            int cc  = crh >> 1;
            int rr  = (crh & 1) * 6 + k18 / 3;
            int t   = k18 % 3;
            float val = 0.f;
            if (rr < RR)
                val = w2[(((cc * RR + rr) * HID) + ph * HCP + hcl) * 3 + t];
            w_s[rem * WPITCH + k18] = val;
        }

        // ---- conv1 + exact gelu -> h_s[hcl][dd], dd in [0,258) ----
        for (int idx = tid; idx < HCP * 258; idx += 512) {
            int hcl = idx / 258;
            int dd  = idx - hcl * 258;
            int hc  = ph * HCP + hcl;
            int dG  = d0 - 1 + dd;
            float s = 0.f;
            if ((unsigned)dG < (unsigned)ND) {
                s = b1[hc];
                const float* wr = w1 + hc * 24;
#pragma unroll
                for (int ci = 0; ci < 8; ++ci) {
                    const float* xr = x_s + ci * HP + dd;  // x[dG-1..dG+1]
                    s = fmaf(xr[0], wr[ci * 3 + 0], s);
                    s = fmaf(xr[1], wr[ci * 3 + 1], s);
                    s = fmaf(xr[2], wr[ci * 3 + 2], s);
                }
                s = 0.5f * s * (1.0f + erff(s * 0.70710678118654752f));
            }
            h_s[hcl * HP + dd] = s;
        }
        __syncthreads();

        // ---- conv2 accumulate over this phase's 88 hidden channels ----
        const float* wrow = w_s + (size_t)(c * 2 + rh) * HCP * WPITCH;
#pragma unroll 1
        for (int hcl = 0; hcl < HCP; ++hcl) {
            const float* wp = wrow + hcl * WPITCH;
            float4 wA = *(const float4*)(wp + 0);    // k0..k3
            float4 wB = *(const float4*)(wp + 4);    // k4..k7
            float4 wC = *(const float4*)(wp + 8);    // k8..k11
            float4 wD = *(const float4*)(wp + 12);   // k12..k15
            float2 wE = *(const float2*)(wp + 16);   // k16..k17

            const float2* hp = (const float2*)(h_s + hcl * HP + dbase);
            float2 f0 = hp[0], f1 = hp[1], f2 = hp[2], f3 = hp[3], f4 = hp[4];
            unsigned long long pk0[4] = {pack2(f0.x, f0.y), pack2(f1.x, f1.y),
                                         pack2(f2.x, f2.y), pack2(f3.x, f3.y)};
            unsigned long long pk1[4] = {pack2(f0.y, f1.x), pack2(f1.y, f2.x),
                                         pack2(f2.y, f3.x), pack2(f3.y, f4.x)};
            unsigned long long pk4 = pack2(f4.x, f4.y);
            // tap2 operands: pk0[1], pk0[2], pk0[3], pk4

#define DO_R(ridx, w0s, w1s, w2s)                                   \
            {                                                       \
                unsigned long long W0 = pack2(w0s, w0s);            \
                unsigned long long W1 = pack2(w1s, w1s);            \
                unsigned long long W2 = pack2(w2s, w2s);            \
                ffma2(acc[ridx][0], pk0[0], W0);                    \
                ffma2(acc[ridx][1], pk0[1], W0);                    \
                ffma2(acc[ridx][2], pk0[2], W0);                    \
                ffma2(acc[ridx][3], pk0[3], W0);                    \
                ffma2(acc[ridx][0], pk1[0], W1);                    \
                ffma2(acc[ridx][1], pk1[1], W1);                    \
                ffma2(acc[ridx][2], pk1[2], W1);                    \
                ffma2(acc[ridx][3], pk1[3], W1);                    \
                ffma2(acc[ridx][0], pk0[1], W2);                    \
                ffma2(acc[ridx][1], pk0[2], W2);                    \
                ffma2(acc[ridx][2], pk0[3], W2);                    \
                ffma2(acc[ridx][3], pk4,    W2);                    \
            }
            DO_R(0, wA.x, wA.y, wA.z)
            DO_R(1, wA.w, wB.x, wB.y)
            DO_R(2, wB.z, wB.w, wC.x)
            DO_R(3, wC.y, wC.z, wC.w)
            DO_R(4, wD.x, wD.y, wD.z)
            DO_R(5, wD.w, wE.x, wE.y)
#undef DO_R
        }
        __syncthreads();   // h_s/w_s consumed; next phase may overwrite
    }

    // ---- epilogue: transpose-stage y into smem (reuse whole smem) ----
    float* y_s = smem;     // [88][YP=261]
#pragma unroll
    for (int r = 0; r < 6; ++r) {
        int rg = rh * 6 + r;
        if (rg < RR) {
            int col = rg * 8 + c;
            float* yr = y_s + (size_t)col * YP + dbase;
#pragma unroll
            for (int i = 0; i < 4; ++i) {
                float2 f = unpack2(acc[r][i]);
                yr[2 * i + 0] = f.x;
                yr[2 * i + 1] = f.y;
            }
        }
    }
    __syncthreads();

    // coalesced global write: A[b][p0..p0+255][r][c]
    size_t gbase = ((size_t)b * NP + (size_t)v * ND + d0) * OC;
    for (int i = tid; i < DT * OC; i += 512) {
        int od  = i / OC;
        int col = i - od * OC;
        g_A[gbase + i] = y_s[(size_t)col * YP + od];
    }
}

// ---------------- gather / interpolation ----------------
__global__ __launch_bounds__(256)
void gather_kernel(const float* __restrict__ idxs, float* __restrict__ out) {
    int j = blockIdx.x * 256 + threadIdx.x;
    if (j >= NIDX) return;

    float t  = idxs[j];
    float il = floorf(t);
    float w  = t - il;
    float w5 = w * 5.0f;
    float fw = floorf(w5);
    float lw = w5 - fw;

    int li = (int)(il * 11.0f + 5.0f + fw);
    int hi = li + 6;
    if (hi >= LL - 1) hi = LL - 2;

    float omlw = 1.0f - lw;
    float omw  = 1.0f - w;

#pragma unroll
    for (int b = 0; b < 2; ++b) {
        const float* Ab = g_A + (size_t)b * (size_t)LL * 8u;
        const float4* plo = (const float4*)(Ab + (size_t)li * 8u);
        const float4* phi = (const float4*)(Ab + (size_t)hi * 8u);
        float4 v0 = __ldg(plo + 0);
        float4 v1 = __ldg(plo + 1);
        float4 v2 = __ldg(plo + 2);
        float4 v3 = __ldg(plo + 3);
        float4 u0 = __ldg(phi + 0);
        float4 u1 = __ldg(phi + 1);
        float4 u2 = __ldg(phi + 2);
        float4 u3 = __ldg(phi + 3);

        float a0[8]  = {v0.x, v0.y, v0.z, v0.w, v1.x, v1.y, v1.z, v1.w};
        float a1[8]  = {v2.x, v2.y, v2.z, v2.w, v3.x, v3.y, v3.z, v3.w};
        float b0[8]  = {u0.x, u0.y, u0.z, u0.w, u1.x, u1.y, u1.z, u1.w};
        float b1v[8] = {u2.x, u2.y, u2.z, u2.w, u3.x, u3.y, u3.z, u3.w};

        size_t obase = (size_t)b * 8u * (size_t)NIDX + (size_t)j;
#pragma unroll
        for (int cc = 0; cc < 8; ++cc) {
            float low  = a0[cc] * omlw + a1[cc]  * lw;
            float high = b0[cc] * omlw + b1v[cc] * lw;
            out[obase + (size_t)cc * (size_t)NIDX] = low * omw + high * w;
        }
    }
}

// ---------------- launch ----------------
extern "C" void kernel_launch(void* const* d_in, const int* in_sizes, int n_in,
                              void* d_out, int out_size) {
    const float* input = (const float*)d_in[0];   // [2,8,360,512]
    const float* idxs  = (const float*)d_in[1];   // [5898240]
    const float* fc1w  = (const float*)d_in[2];   // [176,8,3]
    const float* fc1b  = (const float*)d_in[3];   // [176]
    const float* fc2w  = (const float*)d_in[4];   // [88,176,3]
    const float* fc2b  = (const float*)d_in[5];   // [88]
    float* out = (float*)d_out;

    static const int smem_bytes =
        (8 * HP + HCP * HP + 16 * HCP * WPITCH) * sizeof(float);  // 214016
    cudaFuncSetAttribute(conv_fused, cudaFuncAttributeMaxDynamicSharedMemorySize,
                         smem_bytes);

    conv_fused<<<NB * NV * (ND / DT), 512, smem_bytes>>>(input, fc1w, fc1b,
                                                         fc2w, fc2b);
    gather_kernel<<<NIDX / 256, 256>>>(idxs, out);
}

// round 4
// speedup vs baseline: 1.0051x; 1.0051x over previous
#include <cuda_runtime.h>
#include <cuda_bf16.h>
#include <math.h>

// ---------------- geometry ----------------
#define NB     2
#define NC     8
#define NV     360
#define ND     512
#define RR     11           // taps
#define HID    176          // hidden channels
#define OC     88           // conv2 out channels = RR*NC
#define NP     (NV*ND)      // 184320 sample columns
#define LL     (NP*RR)      // 2027520
#define NIDX   (128*128*360)// 5898240 indices
#define DT     256          // d-tile per block
#define HCP    88           // hidden channels per phase
#define HP     264          // smem pitch (floats) for x_s / h_s (16B mult)
#define YP     265          // y staging pitch (265 mod 32 = 9, gcd(9,32)=1)
#define WPITCH 20           // 18 weights + 2 pad (80B rows, 16B aligned)

// scratch (no cudaMalloc allowed)
__device__ float g_A[2u * (unsigned)LL * 8u];        // [b][p][r][c]  ~130MB

// ---------------- f32x2 helpers ----------------
__device__ __forceinline__ void ffma2(unsigned long long& c,
                                      unsigned long long a,
                                      unsigned long long b) {
    asm("fma.rn.f32x2 %0, %1, %2, %0;" : "+l"(c) : "l"(a), "l"(b));
}
__device__ __forceinline__ unsigned long long pack2(float lo, float hi) {
    unsigned long long r;
    asm("mov.b64 %0, {%1, %2};" : "=l"(r) : "f"(lo), "f"(hi));
    return r;
}
__device__ __forceinline__ float2 unpack2(unsigned long long v) {
    float2 f;
    asm("mov.b64 {%0, %1}, %2;" : "=f"(f.x), "=f"(f.y) : "l"(v));
    return f;
}

// ---------------- fused conv1+gelu+conv2, writes A[b][p][r][c] ----------------
__global__ __launch_bounds__(512, 1)
void conv_fused(const float* __restrict__ input,
                const float* __restrict__ w1,
                const float* __restrict__ b1,
                const float* __restrict__ w2,
                const float* __restrict__ b2) {
    extern __shared__ float smem[];
    float* x_s = smem;                       // [8][264]
    float* h_s = smem + 8 * HP;              // [88][264]
    float* w_s = smem + 8 * HP + HCP * HP;   // [16][88][20]

    const int tid  = threadIdx.x;
    const int blk  = blockIdx.x;
    const int bv   = blk >> 1;
    const int tile = blk & 1;
    const int d0   = tile * DT;
    const int b    = bv / NV;
    const int v    = bv - b * NV;

    // ---- load x halo: x_s[ci][j] = input[b,ci,v, d0-2+j], j in [0,260) ----
    for (int i = tid; i < 8 * HP; i += 512) {
        int ci = i / HP, j = i - ci * HP;
        int dG = d0 - 2 + j;
        float val = 0.f;
        if (j < 260 && (unsigned)dG < (unsigned)ND)
            val = input[(((size_t)(b * NC + ci) * NV + v) * ND) + dG];
        x_s[i] = val;
    }

    const int wid  = tid >> 5;
    const int lane = tid & 31;
    const int c    = wid & 7;        // output channel
    const int rh   = wid >> 3;       // r-half: 0 -> r 0..5, 1 -> r 6..11(pad)
    const int ja   = lane * 4;       // first 4-chunk: od = ja..ja+3
    const int jb   = ja + 128;       // second 4-chunk

    // ---- acc init with bias: acc[r][0..1] chunk A, [2..3] chunk B ----
    unsigned long long acc[6][4];
#pragma unroll
    for (int r = 0; r < 6; ++r) {
        int rg = rh * 6 + r;
        float bb = (rg < RR) ? b2[c * RR + rg] : 0.f;
#pragma unroll
        for (int i = 0; i < 4; ++i) acc[r][i] = pack2(bb, bb);
    }

    __syncthreads();

    for (int ph = 0; ph < 2; ++ph) {
        // ---- stage this phase's fc2 weights into smem ----
        for (int i = tid; i < 16 * HCP * 18; i += 512) {
            int k18 = i % 18;
            int rem = i / 18;            // (c*2+rh)*88 + hcl
            int hcl = rem % HCP;
            int crh = rem / HCP;
            int cc  = crh >> 1;
            int rr  = (crh & 1) * 6 + k18 / 3;
            int t   = k18 % 3;
            float val = 0.f;
            if (rr < RR)
                val = w2[(((cc * RR + rr) * HID) + ph * HCP + hcl) * 3 + t];
            w_s[rem * WPITCH + k18] = val;
        }

        // ---- conv1 + exact gelu -> h_s[hcl][dd], dd in [0,258) ----
        for (int idx = tid; idx < HCP * 258; idx += 512) {
            int hcl = idx / 258;
            int dd  = idx - hcl * 258;
            int hc  = ph * HCP + hcl;
            int dG  = d0 - 1 + dd;
            float s = 0.f;
            if ((unsigned)dG < (unsigned)ND) {
                s = b1[hc];
                const float* wr = w1 + hc * 24;
#pragma unroll
                for (int ci = 0; ci < 8; ++ci) {
                    const float* xr = x_s + ci * HP + dd;  // x[dG-1..dG+1]
                    s = fmaf(xr[0], wr[ci * 3 + 0], s);
                    s = fmaf(xr[1], wr[ci * 3 + 1], s);
                    s = fmaf(xr[2], wr[ci * 3 + 2], s);
                }
                s = 0.5f * s * (1.0f + erff(s * 0.70710678118654752f));
            }
            h_s[hcl * HP + dd] = s;
        }
        __syncthreads();

        // ---- conv2 accumulate over this phase's 88 hidden channels ----
        // taps for output od: t0=h_s[od], t1=h_s[od+1], t2=h_s[od+2]
        const float* wrow = w_s + (size_t)(c * 2 + rh) * HCP * WPITCH;
#pragma unroll 1
        for (int hcl = 0; hcl < HCP; ++hcl) {
            const float* wp = wrow + hcl * WPITCH;
            float4 wA = *(const float4*)(wp + 0);    // k0..k3
            float4 wB = *(const float4*)(wp + 4);    // k4..k7
            float4 wC = *(const float4*)(wp + 8);    // k8..k11
            float4 wD = *(const float4*)(wp + 12);   // k12..k15
            float2 wE = *(const float2*)(wp + 16);   // k16..k17

            const float* hr = h_s + hcl * HP;
            float4 q0 = *(const float4*)(hr + ja);       // h[ja..ja+3]
            float2 e0 = *(const float2*)(hr + ja + 4);   // h[ja+4..5]
            float4 q1 = *(const float4*)(hr + jb);       // h[jb..jb+3]
            float2 e1 = *(const float2*)(hr + jb + 4);   // h[jb+4..5]

            // chunk A tap operands (pairs of consecutive od)
            unsigned long long a0_0 = pack2(q0.x, q0.y); // t0 for (ja,ja+1)
            unsigned long long a1_0 = pack2(q0.y, q0.z); // t1 "
            unsigned long long a2_0 = pack2(q0.z, q0.w); // t2 " / t0 for (ja+2,ja+3)
            unsigned long long b1_0 = pack2(q0.w, e0.x); // t1 for (ja+2,ja+3)
            unsigned long long b2_0 = pack2(e0.x, e0.y); // t2 "
            // chunk B
            unsigned long long a0_1 = pack2(q1.x, q1.y);
            unsigned long long a1_1 = pack2(q1.y, q1.z);
            unsigned long long a2_1 = pack2(q1.z, q1.w);
            unsigned long long b1_1 = pack2(q1.w, e1.x);
            unsigned long long b2_1 = pack2(e1.x, e1.y);

#define DO_R(ridx, w0s, w1s, w2s)                                   \
            {                                                       \
                unsigned long long W0 = pack2(w0s, w0s);            \
                unsigned long long W1 = pack2(w1s, w1s);            \
                unsigned long long W2 = pack2(w2s, w2s);            \
                ffma2(acc[ridx][0], a0_0, W0);                      \
                ffma2(acc[ridx][0], a1_0, W1);                      \
                ffma2(acc[ridx][0], a2_0, W2);                      \
                ffma2(acc[ridx][1], a2_0, W0);                      \
                ffma2(acc[ridx][1], b1_0, W1);                      \
                ffma2(acc[ridx][1], b2_0, W2);                      \
                ffma2(acc[ridx][2], a0_1, W0);                      \
                ffma2(acc[ridx][2], a1_1, W1);                      \
                ffma2(acc[ridx][2], a2_1, W2);                      \
                ffma2(acc[ridx][3], a2_1, W0);                      \
                ffma2(acc[ridx][3], b1_1, W1);                      \
                ffma2(acc[ridx][3], b2_1, W2);                      \
            }
            DO_R(0, wA.x, wA.y, wA.z)
            DO_R(1, wA.w, wB.x, wB.y)
            DO_R(2, wB.z, wB.w, wC.x)
            DO_R(3, wC.y, wC.z, wC.w)
            DO_R(4, wD.x, wD.y, wD.z)
            DO_R(5, wD.w, wE.x, wE.y)
#undef DO_R
        }
        __syncthreads();   // h_s/w_s consumed; next phase may overwrite
    }

    // ---- epilogue: transpose-stage y into smem (reuse whole smem) ----
    float* y_s = smem;     // [88][YP=265]
#pragma unroll
    for (int r = 0; r < 6; ++r) {
        int rg = rh * 6 + r;
        if (rg < RR) {
            int col = rg * 8 + c;
            float* yr = y_s + (size_t)col * YP;
            float2 f;
            f = unpack2(acc[r][0]); yr[ja + 0] = f.x; yr[ja + 1] = f.y;
            f = unpack2(acc[r][1]); yr[ja + 2] = f.x; yr[ja + 3] = f.y;
            f = unpack2(acc[r][2]); yr[jb + 0] = f.x; yr[jb + 1] = f.y;
            f = unpack2(acc[r][3]); yr[jb + 2] = f.x; yr[jb + 3] = f.y;
        }
    }
    __syncthreads();

    // coalesced global write: A[b][p0..p0+255][r][c]
    size_t gbase = ((size_t)b * NP + (size_t)v * ND + d0) * OC;
    for (int i = tid; i < DT * OC; i += 512) {
        int od  = i / OC;
        int col = i - od * OC;
        g_A[gbase + i] = y_s[(size_t)col * YP + od];
    }
}

// ---------------- gather / interpolation ----------------
__global__ __launch_bounds__(256)
void gather_kernel(const float* __restrict__ idxs, float* __restrict__ out) {
    int j = blockIdx.x * 256 + threadIdx.x;
    if (j >= NIDX) return;

    float t  = idxs[j];
    float il = floorf(t);
    float w  = t - il;
    float w5 = w * 5.0f;
    float fw = floorf(w5);
    float lw = w5 - fw;

    int li = (int)(il * 11.0f + 5.0f + fw);
    int hi = li + 6;
    if (hi >= LL - 1) hi = LL - 2;

    float omlw = 1.0f - lw;
    float omw  = 1.0f - w;

#pragma unroll
    for (int b = 0; b < 2; ++b) {
        const float* Ab = g_A + (size_t)b * (size_t)LL * 8u;
        const float4* plo = (const float4*)(Ab + (size_t)li * 8u);
        const float4* phi = (const float4*)(Ab + (size_t)hi * 8u);
        float4 v0 = __ldg(plo + 0);
        float4 v1 = __ldg(plo + 1);
        float4 v2 = __ldg(plo + 2);
        float4 v3 = __ldg(plo + 3);
        float4 u0 = __ldg(phi + 0);
        float4 u1 = __ldg(phi + 1);
        float4 u2 = __ldg(phi + 2);
        float4 u3 = __ldg(phi + 3);

        float a0[8]  = {v0.x, v0.y, v0.z, v0.w, v1.x, v1.y, v1.z, v1.w};
        float a1[8]  = {v2.x, v2.y, v2.z, v2.w, v3.x, v3.y, v3.z, v3.w};
        float b0[8]  = {u0.x, u0.y, u0.z, u0.w, u1.x, u1.y, u1.z, u1.w};
        float b1v[8] = {u2.x, u2.y, u2.z, u2.w, u3.x, u3.y, u3.z, u3.w};

        size_t obase = (size_t)b * 8u * (size_t)NIDX + (size_t)j;
#pragma unroll
        for (int cc = 0; cc < 8; ++cc) {
            float low  = a0[cc] * omlw + a1[cc]  * lw;
            float high = b0[cc] * omlw + b1v[cc] * lw;
            out[obase + (size_t)cc * (size_t)NIDX] = low * omw + high * w;
        }
    }
}

// ---------------- launch ----------------
extern "C" void kernel_launch(void* const* d_in, const int* in_sizes, int n_in,
                              void* d_out, int out_size) {
    const float* input = (const float*)d_in[0];   // [2,8,360,512]
    const float* idxs  = (const float*)d_in[1];   // [5898240]
    const float* fc1w  = (const float*)d_in[2];   // [176,8,3]
    const float* fc1b  = (const float*)d_in[3];   // [176]
    const float* fc2w  = (const float*)d_in[4];   // [88,176,3]
    const float* fc2b  = (const float*)d_in[5];   // [88]
    float* out = (float*)d_out;

    static const int smem_bytes =
        (8 * HP + HCP * HP + 16 * HCP * WPITCH) * sizeof(float);  // 214016
    cudaFuncSetAttribute(conv_fused, cudaFuncAttributeMaxDynamicSharedMemorySize,
                         smem_bytes);

    conv_fused<<<NB * NV * (ND / DT), 512, smem_bytes>>>(input, fc1w, fc1b,
                                                         fc2w, fc2b);
    gather_kernel<<<NIDX / 256, 256>>>(idxs, out);
}

// round 6
// speedup vs baseline: 2.0002x; 1.9900x over previous
#include <cuda_runtime.h>
#include <cuda_bf16.h>
#include <math.h>
#include <stdint.h>

// ---------------- geometry ----------------
#define NB     2
#define NC     8
#define NV     360
#define ND     512
#define RR     11
#define HID    176
#define OC     88
#define NP     (NV*ND)
#define LL     (NP*RR)
#define NIDX   (128*128*360)

#define MT     128          // d positions per block
#define KPIT   184          // bf16 col pitch (368B rows: conflict-free ldmatrix)
#define XP     136          // x_s pitch (floats)

// SMEM byte offsets (ldmatrix regions 16B aligned)
#define SM_X     0          // 8*136*4      = 4352
#define SM_W1    4352       // 176*25*4     = 17600
#define SM_B1    21952      // 176*4        = 704
#define SM_B2    22656      // 88*4 -> pad  = 384
#define SM_HBH   23040      // 132*184*2    = 48576
#define SM_HBL   71616      // 48576
#define SM_BSH   120192     // 96*184*2     = 35328
#define SM_BSL   155520     // 35328
#define SM_TOT   190848

// scratch (no cudaMalloc allowed)
__device__ float g_A[2u * (unsigned)LL * 8u];          // gather table ~130MB
__device__ __align__(16) __nv_bfloat16 g_Bhi[3 * 96 * KPIT];
__device__ __align__(16) __nv_bfloat16 g_Blo[3 * 96 * KPIT];

// ---------------- helpers ----------------
__device__ __forceinline__ uint32_t smem_u32(const void* p) {
    uint32_t a;
    asm("{ .reg .u64 t; cvta.to.shared.u64 t, %1; cvt.u32.u64 %0, t; }"
        : "=r"(a) : "l"(p));
    return a;
}

#define LDM4(d, addr)                                                        \
    asm volatile("ldmatrix.sync.aligned.m8n8.x4.shared.b16 "                 \
                 "{%0,%1,%2,%3}, [%4];"                                      \
                 : "=r"((d)[0]), "=r"((d)[1]), "=r"((d)[2]), "=r"((d)[3])    \
                 : "r"(addr) : "memory")

#define MMA(c, a, b0, b1)                                                    \
    asm volatile("mma.sync.aligned.m16n8k16.row.col.f32.bf16.bf16.f32 "      \
                 "{%0,%1,%2,%3},{%4,%5,%6,%7},{%8,%9},{%0,%1,%2,%3};"        \
                 : "+f"((c)[0]), "+f"((c)[1]), "+f"((c)[2]), "+f"((c)[3])    \
                 : "r"((a)[0]), "r"((a)[1]), "r"((a)[2]), "r"((a)[3]),       \
                   "r"(b0), "r"(b1))

// ---- prep: fc2_w [88][176][3] -> per-tap bf16 hi/lo images [t][96][184] ----
__global__ void prep_B(const float* __restrict__ w2) {
    int i = blockIdx.x * 256 + threadIdx.x;     // over 3*96*184
    if (i >= 3 * 96 * KPIT) return;
    int k = i % KPIT;
    int n = (i / KPIT) % 96;
    int t = i / (KPIT * 96);
    float v = 0.f;
    if (n < OC && k < HID) v = w2[((size_t)n * HID + k) * 3 + t];
    __nv_bfloat16 hi = __float2bfloat16(v);
    __nv_bfloat16 lo = __float2bfloat16(v - __bfloat162float(hi));
    g_Bhi[i] = hi;
    g_Blo[i] = lo;
}

// ---------------- fused conv1+gelu + warp-MMA conv2 ----------------
__global__ __launch_bounds__(256, 1)
void conv_tc(const float* __restrict__ input,
             const float* __restrict__ w1,
             const float* __restrict__ b1,
             const float* __restrict__ b2) {
    extern __shared__ char smem[];
    const uint32_t sb = smem_u32(smem);
    float* x_s = (float*)(smem + SM_X);
    float* w1s = (float*)(smem + SM_W1);
    float* b1s = (float*)(smem + SM_B1);
    float* b2s = (float*)(smem + SM_B2);

    const int tid  = threadIdx.x;
    const int wid  = tid >> 5;
    const int lane = tid & 31;
    const int blk  = blockIdx.x;
    const int tile = blk & 3;
    const int bv   = blk >> 2;
    const int b    = bv / NV;
    const int v    = bv - b * NV;
    const int d0   = tile * MT;

    // ---- stage x halo: x_s[ci][j] = input[b,ci,v, d0-2+j] ----
    for (int i = tid; i < 8 * XP; i += 256) {
        int ci = i / XP, j = i - ci * XP;
        int dG = d0 - 2 + j;
        float val = 0.f;
        if ((unsigned)dG < (unsigned)ND)
            val = input[(((size_t)(b * NC + ci) * NV + v) * ND) + dG];
        x_s[i] = val;
    }
    // stage conv1 weights (pitch 25: conflict-free), biases
    for (int i = tid; i < HID * 24; i += 256)
        w1s[(i / 24) * 25 + (i % 24)] = w1[i];
    for (int i = tid; i < HID; i += 256) b1s[i] = b1[i];
    for (int i = tid; i < OC; i += 256)  b2s[i] = b2[i];
    __syncthreads();

    // ---- conv1 + exact gelu -> Hb[dd][hc] bf16 hi/lo, dd = m+t, hc contig ----
    const float inv_sqrt2 = 0.70710678118654752f;
    for (int u = tid; u < 33 * HID; u += 256) {
        int hc  = u % HID;            // lanes -> consecutive hc (coalesced writes)
        int ch  = u / HID;
        int ddb = ch * 4;

        float wr[24];
#pragma unroll
        for (int i = 0; i < 24; ++i) wr[i] = w1s[hc * 25 + i];
        float bias = b1s[hc];

        float a4[4] = {bias, bias, bias, bias};
#pragma unroll
        for (int ci = 0; ci < 8; ++ci) {
            const float* xr = x_s + ci * XP + ddb;
            float4 xa = *(const float4*)xr;
            float2 xb = *(const float2*)(xr + 4);
            float xv[6] = {xa.x, xa.y, xa.z, xa.w, xb.x, xb.y};
#pragma unroll
            for (int q = 0; q < 4; ++q) {
                a4[q] = fmaf(xv[q + 0], wr[ci * 3 + 0], a4[q]);
                a4[q] = fmaf(xv[q + 1], wr[ci * 3 + 1], a4[q]);
                a4[q] = fmaf(xv[q + 2], wr[ci * 3 + 2], a4[q]);
            }
        }
#pragma unroll
        for (int q = 0; q < 4; ++q) {
            int dd = ddb + q;                 // dd in [0,132)
            int dG = d0 - 1 + dd;
            float s = 0.f;
            if ((unsigned)dG < (unsigned)ND) {
                s = a4[q];
                s = 0.5f * s * (1.0f + erff(s * inv_sqrt2));
            }
            __nv_bfloat16 hi = __float2bfloat16(s);
            __nv_bfloat16 lo = __float2bfloat16(s - __bfloat162float(hi));
            size_t off = (size_t)dd * KPIT + hc;
            *((__nv_bfloat16*)(smem + SM_HBH) + off) = hi;
            *((__nv_bfloat16*)(smem + SM_HBL) + off) = lo;
        }
    }

    // ---- warp MMA: 4x2 warp grid, warp tile 32m x 48n ----
    const int m0 = (wid & 3) * 32;
    const int n0 = (wid >> 2) * 48;

    float acc[2][6][4];
#pragma unroll
    for (int i = 0; i < 2; ++i)
#pragma unroll
        for (int j = 0; j < 6; ++j)
#pragma unroll
            for (int q = 0; q < 4; ++q) acc[i][j][q] = 0.f;

    // ldmatrix address bases (per thread)
    const uint32_t aRel = ((uint32_t)(m0 + (lane & 15)) * KPIT +
                           (uint32_t)(lane >> 4) * 8) * 2;
    const int g = lane >> 3;
    const uint32_t bRel = ((uint32_t)(n0 + (g >> 1) * 8 + (lane & 7)) * KPIT +
                           (uint32_t)(g & 1) * 8) * 2;
    const uint32_t ROWB = KPIT * 2;        // 368 bytes per row

    for (int t = 0; t < 3; ++t) {
        __syncthreads();   // previous phase's ldmatrix reads done
        // stage B_t (hi+lo) from prepped global image
        {
            const float4* shb = (const float4*)(g_Bhi + (size_t)t * 96 * KPIT);
            const float4* slb = (const float4*)(g_Blo + (size_t)t * 96 * KPIT);
            float4* dh = (float4*)(smem + SM_BSH);
            float4* dl = (float4*)(smem + SM_BSL);
            for (int i = tid; i < (96 * KPIT * 2) / 16; i += 256) {
                dh[i] = shb[i];
                dl[i] = slb[i];
            }
        }
        __syncthreads();

        uint32_t aH = sb + SM_HBH + aRel + (uint32_t)t * ROWB;
        uint32_t aL = sb + SM_HBL + aRel + (uint32_t)t * ROWB;
        uint32_t bH = sb + SM_BSH + bRel;
        uint32_t bL = sb + SM_BSL + bRel;

#pragma unroll 1
        for (int ks = 0; ks < 11; ++ks) {
            uint32_t ah0[4], ah1[4], al0[4], al1[4];
            LDM4(ah0, aH);
            LDM4(ah1, aH + 16 * ROWB);
            LDM4(al0, aL);
            LDM4(al1, aL + 16 * ROWB);
            uint32_t bh[3][4], bl[3][4];
            LDM4(bh[0], bH);
            LDM4(bh[1], bH + 16 * ROWB);
            LDM4(bh[2], bH + 32 * ROWB);
            LDM4(bl[0], bL);
            LDM4(bl[1], bL + 16 * ROWB);
            LDM4(bl[2], bL + 32 * ROWB);

#pragma unroll
            for (int j = 0; j < 6; ++j) {
                const int jj = j >> 1, pp = (j & 1) * 2;
                MMA(acc[0][j], ah0, bh[jj][pp], bh[jj][pp + 1]);
                MMA(acc[0][j], ah0, bl[jj][pp], bl[jj][pp + 1]);
                MMA(acc[0][j], al0, bh[jj][pp], bh[jj][pp + 1]);
                MMA(acc[1][j], ah1, bh[jj][pp], bh[jj][pp + 1]);
                MMA(acc[1][j], ah1, bl[jj][pp], bl[jj][pp + 1]);
                MMA(acc[1][j], al1, bh[jj][pp], bh[jj][pp + 1]);
            }
            aH += 32; aL += 32; bH += 32; bL += 32;   // next k16 (32 bytes)
        }
    }
    __syncthreads();   // all Hb reads done; reuse region for y staging

    // ---- epilogue: acc + bias, permute oc -> (rr*8+ci), stage, store ----
    float* y_s = (float*)(smem + SM_HBH);   // [128][89]
    const int rbase = (lane >> 2);
    const int cbase = (lane & 3) * 2;
#pragma unroll
    for (int i = 0; i < 2; ++i) {
#pragma unroll
        for (int j = 0; j < 6; ++j) {
            int col0 = n0 + j * 8 + cbase;
#pragma unroll
            for (int rh2 = 0; rh2 < 2; ++rh2) {
                int row = m0 + i * 16 + rbase + rh2 * 8;
#pragma unroll
                for (int ch2 = 0; ch2 < 2; ++ch2) {
                    int col = col0 + ch2;
                    if (col < OC) {
                        int ci = col / RR, rm = col - ci * RR;
                        y_s[(size_t)row * 89 + rm * 8 + ci] =
                            acc[i][j][rh2 * 2 + ch2] + b2s[col];
                    }
                }
            }
        }
    }
    __syncthreads();

    // coalesced global write: g_A[(b*NP + v*512 + d0 + m)*88 + (r*8+c)]
    size_t gbase = ((size_t)b * NP + (size_t)v * ND + d0) * OC;
    for (int i = tid; i < MT * OC; i += 256) {
        int od  = i / OC;
        int col = i - od * OC;
        g_A[gbase + i] = y_s[(size_t)od * 89 + col];
    }
}

// ---------------- gather / interpolation (71% DRAM, unchanged) ----------------
__global__ __launch_bounds__(256)
void gather_kernel(const float* __restrict__ idxs, float* __restrict__ out) {
    int j = blockIdx.x * 256 + threadIdx.x;
    if (j >= NIDX) return;

    float t  = idxs[j];
    float il = floorf(t);
    float w  = t - il;
    float w5 = w * 5.0f;
    float fw = floorf(w5);
    float lw = w5 - fw;

    int li = (int)(il * 11.0f + 5.0f + fw);
    int hi = li + 6;
    if (hi >= LL - 1) hi = LL - 2;

    float omlw = 1.0f - lw;
    float omw  = 1.0f - w;

#pragma unroll
    for (int b = 0; b < 2; ++b) {
        const float* Ab = g_A + (size_t)b * (size_t)LL * 8u;
        const float4* plo = (const float4*)(Ab + (size_t)li * 8u);
        const float4* phi = (const float4*)(Ab + (size_t)hi * 8u);
        float4 v0 = __ldg(plo + 0);
        float4 v1 = __ldg(plo + 1);
        float4 v2 = __ldg(plo + 2);
        float4 v3 = __ldg(plo + 3);
        float4 u0 = __ldg(phi + 0);
        float4 u1 = __ldg(phi + 1);
        float4 u2 = __ldg(phi + 2);
        float4 u3 = __ldg(phi + 3);

        float a0[8]  = {v0.x, v0.y, v0.z, v0.w, v1.x, v1.y, v1.z, v1.w};
        float a1[8]  = {v2.x, v2.y, v2.z, v2.w, v3.x, v3.y, v3.z, v3.w};
        float b0[8]  = {u0.x, u0.y, u0.z, u0.w, u1.x, u1.y, u1.z, u1.w};
        float b1v[8] = {u2.x, u2.y, u2.z, u2.w, u3.x, u3.y, u3.z, u3.w};

        size_t obase = (size_t)b * 8u * (size_t)NIDX + (size_t)j;
#pragma unroll
        for (int cc = 0; cc < 8; ++cc) {
            float low  = a0[cc] * omlw + a1[cc]  * lw;
            float high = b0[cc] * omlw + b1v[cc] * lw;
            out[obase + (size_t)cc * (size_t)NIDX] = low * omw + high * w;
        }
    }
}

// ---------------- launch ----------------
extern "C" void kernel_launch(void* const* d_in, const int* in_sizes, int n_in,
                              void* d_out, int out_size) {
    const float* input = (const float*)d_in[0];
    const float* idxs  = (const float*)d_in[1];
    const float* fc1w  = (const float*)d_in[2];
    const float* fc1b  = (const float*)d_in[3];
    const float* fc2w  = (const float*)d_in[4];
    const float* fc2b  = (const float*)d_in[5];
    float* out = (float*)d_out;

    cudaFuncSetAttribute(conv_tc, cudaFuncAttributeMaxDynamicSharedMemorySize,
                         SM_TOT);

    prep_B<<<(3 * 96 * KPIT + 255) / 256, 256>>>(fc2w);
    conv_tc<<<NB * NV * (ND / MT), 256, SM_TOT>>>(input, fc1w, fc1b, fc2b);
    gather_kernel<<<NIDX / 256, 256>>>(idxs, out);
}

// round 7
// speedup vs baseline: 2.7512x; 1.3755x over previous
#include <cuda_runtime.h>
#include <cuda_bf16.h>
#include <cuda_fp16.h>
#include <math.h>
#include <stdint.h>

// ---------------- geometry ----------------
#define NB     2
#define NC     8
#define NV     360
#define ND     512
#define RR     11
#define HID    176
#define OC     88
#define NP     (NV*ND)
#define LL     (NP*RR)
#define NIDX   (128*128*360)

#define MT     128          // d positions per block
#define KPIT   184          // bf16 col pitch (368B rows: odd 16B-segments -> conflict-free ldmatrix)
#define XP     136          // x_s pitch (floats)
#define NTHR   384          // 12 warps

// SMEM byte offsets
#define SM_X     0          // 8*136*4      = 4352
#define SM_W1    4352       // 176*25*4     = 17600
#define SM_B1    21952      // 176*4        = 704
#define SM_B2    22656      // 88*4 pad     = 384
#define SM_HBH   23040      // 132*184*2    = 48576
#define SM_HBL   71616      // 48576
#define SM_BSH   120192     // 96*184*2     = 35328
#define SM_BSL   155520     // 35328
#define SM_TOT   190848

#define BIMG_HALVES (96 * KPIT)             // 17664 per split per tap

// scratch (no cudaMalloc allowed)
__device__ __half g_Ah[2u * (unsigned)LL * 8u];                  // fp16 table ~65MB
__device__ __align__(16) __nv_bfloat16 g_Bimg[3 * 2 * BIMG_HALVES];

// ---------------- helpers ----------------
__device__ __forceinline__ uint32_t smem_u32(const void* p) {
    uint32_t a;
    asm("{ .reg .u64 t; cvta.to.shared.u64 t, %1; cvt.u32.u64 %0, t; }"
        : "=r"(a) : "l"(p));
    return a;
}

#define LDM4(d, addr)                                                        \
    asm volatile("ldmatrix.sync.aligned.m8n8.x4.shared.b16 "                 \
                 "{%0,%1,%2,%3}, [%4];"                                      \
                 : "=r"((d)[0]), "=r"((d)[1]), "=r"((d)[2]), "=r"((d)[3])    \
                 : "r"(addr) : "memory")

#define MMA(c, a, b0, b1)                                                    \
    asm volatile("mma.sync.aligned.m16n8k16.row.col.f32.bf16.bf16.f32 "      \
                 "{%0,%1,%2,%3},{%4,%5,%6,%7},{%8,%9},{%0,%1,%2,%3};"        \
                 : "+f"((c)[0]), "+f"((c)[1]), "+f"((c)[2]), "+f"((c)[3])    \
                 : "r"((a)[0]), "r"((a)[1]), "r"((a)[2]), "r"((a)[3]),       \
                   "r"(b0), "r"(b1))

#define CP16(dst, src)                                                       \
    asm volatile("cp.async.cg.shared.global [%0], [%1], 16;"                 \
                 :: "r"(dst), "l"(src) : "memory")
#define CPCOMMIT() asm volatile("cp.async.commit_group;" ::: "memory")
#define CPWAIT0()  asm volatile("cp.async.wait_group 0;"  ::: "memory")

// ---- prep: fc2_w [88][176][3] -> per-tap contiguous bf16 hi/lo images ----
__global__ void prep_B(const float* __restrict__ w2) {
    int i = blockIdx.x * 256 + threadIdx.x;     // over 3*96*184
    if (i >= 3 * BIMG_HALVES) return;
    int k = i % KPIT;
    int n = (i / KPIT) % 96;
    int t = i / BIMG_HALVES;
    float v = 0.f;
    if (n < OC && k < HID) v = w2[((size_t)n * HID + k) * 3 + t];
    __nv_bfloat16 hi = __float2bfloat16(v);
    __nv_bfloat16 lo = __float2bfloat16(v - __bfloat162float(hi));
    size_t base = (size_t)t * 2 * BIMG_HALVES + (size_t)n * KPIT + k;
    g_Bimg[base]               = hi;
    g_Bimg[base + BIMG_HALVES] = lo;
}

// ---------------- fused conv1+gelu + warp-MMA conv2 -> fp16 table ----------------
__global__ __launch_bounds__(NTHR, 1)
void conv_tc(const float* __restrict__ input,
             const float* __restrict__ w1,
             const float* __restrict__ b1,
             const float* __restrict__ b2) {
    extern __shared__ char smem[];
    const uint32_t sb = smem_u32(smem);
    float* x_s = (float*)(smem + SM_X);
    float* w1s = (float*)(smem + SM_W1);
    float* b1s = (float*)(smem + SM_B1);
    float* b2s = (float*)(smem + SM_B2);

    const int tid  = threadIdx.x;
    const int wid  = tid >> 5;
    const int lane = tid & 31;
    const int blk  = blockIdx.x;
    const int tile = blk & 3;
    const int bv   = blk >> 2;
    const int b    = bv / NV;
    const int v    = bv - b * NV;
    const int d0   = tile * MT;

    // ---- stage x halo, conv1 weights, biases ----
    for (int i = tid; i < 8 * XP; i += NTHR) {
        int ci = i / XP, j = i - ci * XP;
        int dG = d0 - 2 + j;
        float val = 0.f;
        if ((unsigned)dG < (unsigned)ND)
            val = input[(((size_t)(b * NC + ci) * NV + v) * ND) + dG];
        x_s[i] = val;
    }
    for (int i = tid; i < HID * 24; i += NTHR)
        w1s[(i / 24) * 25 + (i % 24)] = w1[i];
    for (int i = tid; i < HID; i += NTHR) b1s[i] = b1[i];
    for (int i = tid; i < OC; i += NTHR)  b2s[i] = b2[i];

    // ---- async stage B tap 0 (overlaps with conv1) ----
    {
        const char* src = (const char*)g_Bimg;           // tap 0 contiguous hi+lo
        for (int i = tid; i < (2 * BIMG_HALVES * 2) / 16; i += NTHR)
            CP16(sb + SM_BSH + i * 16, src + i * 16);
        CPCOMMIT();
    }
    __syncthreads();

    // ---- conv1 + exact gelu -> Hb[dd][hc] bf16 hi/lo ----
    const float inv_sqrt2 = 0.70710678118654752f;
    for (int u = tid; u < 33 * HID; u += NTHR) {
        int hc  = u % HID;
        int ch  = u / HID;
        int ddb = ch * 4;

        float wr[24];
#pragma unroll
        for (int i = 0; i < 24; ++i) wr[i] = w1s[hc * 25 + i];
        float bias = b1s[hc];

        float a4[4] = {bias, bias, bias, bias};
#pragma unroll
        for (int ci = 0; ci < 8; ++ci) {
            const float* xr = x_s + ci * XP + ddb;
            float4 xa = *(const float4*)xr;
            float2 xb = *(const float2*)(xr + 4);
            float xv[6] = {xa.x, xa.y, xa.z, xa.w, xb.x, xb.y};
#pragma unroll
            for (int q = 0; q < 4; ++q) {
                a4[q] = fmaf(xv[q + 0], wr[ci * 3 + 0], a4[q]);
                a4[q] = fmaf(xv[q + 1], wr[ci * 3 + 1], a4[q]);
                a4[q] = fmaf(xv[q + 2], wr[ci * 3 + 2], a4[q]);
            }
        }
#pragma unroll
        for (int q = 0; q < 4; ++q) {
            int dd = ddb + q;                 // dd in [0,132)
            int dG = d0 - 1 + dd;
            float s = 0.f;
            if ((unsigned)dG < (unsigned)ND) {
                s = a4[q];
                s = 0.5f * s * (1.0f + erff(s * inv_sqrt2));
            }
            __nv_bfloat16 hi = __float2bfloat16(s);
            __nv_bfloat16 lo = __float2bfloat16(s - __bfloat162float(hi));
            size_t off = (size_t)dd * KPIT + hc;
            *((__nv_bfloat16*)(smem + SM_HBH) + off) = hi;
            *((__nv_bfloat16*)(smem + SM_HBL) + off) = lo;
        }
    }
    CPWAIT0();
    __syncthreads();   // Hb + B0 ready

    // ---- warp MMA: 4x3 warp grid, warp tile 32m x 32n ----
    const int m0 = (wid & 3) * 32;
    const int n0 = (wid >> 2) * 32;

    float acc[2][4][4];
#pragma unroll
    for (int i = 0; i < 2; ++i)
#pragma unroll
        for (int j = 0; j < 4; ++j)
#pragma unroll
            for (int q = 0; q < 4; ++q) acc[i][j][q] = 0.f;

    const uint32_t aRel = ((uint32_t)(m0 + (lane & 15)) * KPIT +
                           (uint32_t)(lane >> 4) * 8) * 2;
    const int g = lane >> 3;
    const uint32_t bRel = ((uint32_t)(n0 + (g >> 1) * 8 + (lane & 7)) * KPIT +
                           (uint32_t)(g & 1) * 8) * 2;
    const uint32_t ROWB = KPIT * 2;        // 368 bytes

    for (int t = 0; t < 3; ++t) {
        uint32_t aH = sb + SM_HBH + aRel + (uint32_t)t * ROWB;
        uint32_t aL = sb + SM_HBL + aRel + (uint32_t)t * ROWB;
        uint32_t bH = sb + SM_BSH + bRel;
        uint32_t bL = sb + SM_BSL + bRel;

#pragma unroll 1
        for (int ks = 0; ks < 11; ++ks) {
            uint32_t ah0[4], ah1[4], al0[4], al1[4];
            LDM4(ah0, aH);
            LDM4(ah1, aH + 16 * ROWB);
            LDM4(al0, aL);
            LDM4(al1, aL + 16 * ROWB);
            uint32_t bh[2][4], bl[2][4];
            LDM4(bh[0], bH);
            LDM4(bh[1], bH + 16 * ROWB);
            LDM4(bl[0], bL);
            LDM4(bl[1], bL + 16 * ROWB);

#pragma unroll
            for (int j = 0; j < 4; ++j) {
                const int jj = j >> 1, pp = (j & 1) * 2;
                MMA(acc[0][j], ah0, bh[jj][pp], bh[jj][pp + 1]);
                MMA(acc[0][j], ah0, bl[jj][pp], bl[jj][pp + 1]);
                MMA(acc[0][j], al0, bh[jj][pp], bh[jj][pp + 1]);
                MMA(acc[1][j], ah1, bh[jj][pp], bh[jj][pp + 1]);
                MMA(acc[1][j], ah1, bl[jj][pp], bl[jj][pp + 1]);
                MMA(acc[1][j], al1, bh[jj][pp], bh[jj][pp + 1]);
            }
            aH += 32; aL += 32; bH += 32; bL += 32;
        }

        if (t < 2) {
            __syncthreads();   // B buffer free
            const char* src = (const char*)g_Bimg
                            + (size_t)(t + 1) * 2 * BIMG_HALVES * 2;
            for (int i = tid; i < (2 * BIMG_HALVES * 2) / 16; i += NTHR)
                CP16(sb + SM_BSH + i * 16, src + i * 16);
            CPCOMMIT();
            CPWAIT0();
            __syncthreads();
        }
    }
    __syncthreads();   // all Hb reads done; reuse region for y staging

    // ---- epilogue: acc + bias -> fp16, permute oc -> (rr*8+ci) ----
    __half* y_s = (__half*)(smem + SM_HBH);   // [128][96] halves
    const int rbase = (lane >> 2);
    const int cbase = (lane & 3) * 2;
#pragma unroll
    for (int i = 0; i < 2; ++i) {
#pragma unroll
        for (int j = 0; j < 4; ++j) {
            int col0 = n0 + j * 8 + cbase;
#pragma unroll
            for (int rh2 = 0; rh2 < 2; ++rh2) {
                int row = m0 + i * 16 + rbase + rh2 * 8;
#pragma unroll
                for (int ch2 = 0; ch2 < 2; ++ch2) {
                    int col = col0 + ch2;
                    if (col < OC) {
                        int ci = col / RR, rm = col - ci * RR;
                        y_s[(size_t)row * 96 + rm * 8 + ci] =
                            __float2half(acc[i][j][rh2 * 2 + ch2] + b2s[col]);
                    }
                }
            }
        }
    }
    __syncthreads();

    // coalesced global write: g_Ah[(b*NP + v*512 + d0 + m)*88 + (r*8+c)]
    size_t gbase = ((size_t)b * NP + (size_t)v * ND + d0) * OC;
    for (int i = tid; i < MT * (OC / 2); i += NTHR) {
        int od = i / (OC / 2);
        int cu = i - od * (OC / 2);
        ((uint32_t*)(g_Ah + gbase + (size_t)od * OC))[cu] =
            ((const uint32_t*)(y_s + (size_t)od * 96))[cu];
    }
}

// ---------------- gather / interpolation (fp16 table) ----------------
__global__ __launch_bounds__(256)
void gather_kernel(const float* __restrict__ idxs, float* __restrict__ out) {
    int j = blockIdx.x * 256 + threadIdx.x;
    if (j >= NIDX) return;

    float t  = idxs[j];
    float il = floorf(t);
    float w  = t - il;
    float w5 = w * 5.0f;
    float fw = floorf(w5);
    float lw = w5 - fw;

    int li = (int)(il * 11.0f + 5.0f + fw);
    int hi = li + 6;
    if (hi >= LL - 1) hi = LL - 2;

    float omlw = 1.0f - lw;
    float omw  = 1.0f - w;

#pragma unroll
    for (int b = 0; b < 2; ++b) {
        const __half* Ab = g_Ah + (size_t)b * (size_t)LL * 8u;
        uint4 va = __ldg((const uint4*)(Ab + (size_t)li * 8u));
        uint4 vb = __ldg((const uint4*)(Ab + (size_t)(li + 1) * 8u));
        uint4 ua = __ldg((const uint4*)(Ab + (size_t)hi * 8u));
        uint4 ub = __ldg((const uint4*)(Ab + (size_t)(hi + 1) * 8u));

        size_t obase = (size_t)b * 8u * (size_t)NIDX + (size_t)j;
#pragma unroll
        for (int p = 0; p < 4; ++p) {
            float2 a0 = __half22float2(((const __half2*)&va)[p]);
            float2 a1 = __half22float2(((const __half2*)&vb)[p]);
            float2 c0 = __half22float2(((const __half2*)&ua)[p]);
            float2 c1 = __half22float2(((const __half2*)&ub)[p]);

            float lowx  = a0.x * omlw + a1.x * lw;
            float lowy  = a0.y * omlw + a1.y * lw;
            float highx = c0.x * omlw + c1.x * lw;
            float highy = c0.y * omlw + c1.y * lw;

            out[obase + (size_t)(2 * p + 0) * NIDX] = lowx * omw + highx * w;
            out[obase + (size_t)(2 * p + 1) * NIDX] = lowy * omw + highy * w;
        }
    }
}

// ---------------- launch ----------------
extern "C" void kernel_launch(void* const* d_in, const int* in_sizes, int n_in,
                              void* d_out, int out_size) {
    const float* input = (const float*)d_in[0];
    const float* idxs  = (const float*)d_in[1];
    const float* fc1w  = (const float*)d_in[2];
    const float* fc1b  = (const float*)d_in[3];
    const float* fc2w  = (const float*)d_in[4];
    const float* fc2b  = (const float*)d_in[5];
    float* out = (float*)d_out;

    cudaFuncSetAttribute(conv_tc, cudaFuncAttributeMaxDynamicSharedMemorySize,
                         SM_TOT);

    prep_B<<<(3 * BIMG_HALVES + 255) / 256, 256>>>(fc2w);
    conv_tc<<<NB * NV * (ND / MT), NTHR, SM_TOT>>>(input, fc1w, fc1b, fc2b);
    gather_kernel<<<NIDX / 256, 256>>>(idxs, out);
}

// round 9
// speedup vs baseline: 3.6434x; 1.3243x over previous
#include <cuda_runtime.h>
#include <cuda_bf16.h>
#include <cuda_fp16.h>
#include <math.h>
#include <stdint.h>

// ---------------- geometry ----------------
#define NB     2
#define NC     8
#define NV     360
#define ND     512
#define RR     11
#define HID    176
#define OC     88
#define NP     (NV*ND)
#define LL     (NP*RR)
#define NIDX   (128*128*360)

#define MT     128          // d positions per block
#define KPIT   184          // fp16 col pitch (368B rows -> conflict-free ldmatrix)
#define XP     136          // x_s pitch (floats)
#define NTHR   384          // 12 warps

// SMEM byte offsets
#define SM_X     0          // 8*136*4      = 4352
#define SM_W1    4352       // 176*25*4     = 17600
#define SM_B1    21952      // 176*4        = 704
#define SM_B2    22656      // 88*4 pad     = 384
#define SM_HB    23040      // 132*184*2    = 48576   (H fp16)
#define SM_BS    71616      // 96*184*2     = 35328   (one B split)
#define SM_TOT   106944

#define BIMG    (96 * KPIT)             // 17664 halves per split per tap
#define BCHUNK  (BIMG * 2)              // 35328 bytes

// scratch (no cudaMalloc allowed)
__device__ __half g_Ah[2u * (unsigned)LL * 8u];          // fp16 table ~65MB
__device__ __align__(16) __half g_Bimg[3 * 2 * BIMG];    // [t][split][96*184]

// ---------------- helpers ----------------
__device__ __forceinline__ uint32_t smem_u32(const void* p) {
    uint32_t a;
    asm("{ .reg .u64 t; cvta.to.shared.u64 t, %1; cvt.u32.u64 %0, t; }"
        : "=r"(a) : "l"(p));
    return a;
}

#define LDM4(d, addr)                                                        \
    asm volatile("ldmatrix.sync.aligned.m8n8.x4.shared.b16 "                 \
                 "{%0,%1,%2,%3}, [%4];"                                      \
                 : "=r"((d)[0]), "=r"((d)[1]), "=r"((d)[2]), "=r"((d)[3])    \
                 : "r"(addr) : "memory")

#define MMA(c, a, b0, b1)                                                    \
    asm volatile("mma.sync.aligned.m16n8k16.row.col.f32.f16.f16.f32 "        \
                 "{%0,%1,%2,%3},{%4,%5,%6,%7},{%8,%9},{%0,%1,%2,%3};"        \
                 : "+f"((c)[0]), "+f"((c)[1]), "+f"((c)[2]), "+f"((c)[3])    \
                 : "r"((a)[0]), "r"((a)[1]), "r"((a)[2]), "r"((a)[3]),       \
                   "r"(b0), "r"(b1))

#define CP16(dst, src)                                                       \
    asm volatile("cp.async.cg.shared.global [%0], [%1], 16;"                 \
                 :: "r"(dst), "l"(src) : "memory")
#define CPCOMMIT() asm volatile("cp.async.commit_group;" ::: "memory")
#define CPWAIT0()  asm volatile("cp.async.wait_group 0;"  ::: "memory")

// exact-accuracy cheap gelu: erf via A&S 7.1.26 (|eps| <= 1.5e-7)
__device__ __forceinline__ float gelu_f(float x) {
    float z = x * 0.70710678118654752f;
    float a = fabsf(z);
    float t = __fdividef(1.0f, fmaf(0.3275911f, a, 1.0f));
    float p = t * fmaf(t, fmaf(t, fmaf(t, fmaf(t, 1.061405429f, -1.453152027f),
                                       1.421413741f), -0.284496736f),
                       0.254829592f);
    float e = __expf(-a * a);
    float erfa = fmaf(-p, e, 1.0f);
    float erfz = copysignf(erfa, z);
    return 0.5f * x * (1.0f + erfz);
}

// ---- prep: fc2_w [88][176][3] -> per (tap,split) contiguous fp16 images ----
__global__ void prep_B(const float* __restrict__ w2) {
    int i = blockIdx.x * 256 + threadIdx.x;     // over 3*96*184
    if (i >= 3 * BIMG) return;
    int k = i % KPIT;
    int n = (i / KPIT) % 96;
    int t = i / BIMG;
    float v = 0.f;
    if (n < OC && k < HID) v = w2[((size_t)n * HID + k) * 3 + t];
    __half hi = __float2half_rn(v);
    __half lo = __float2half_rn(v - __half2float(hi));
    size_t base = (size_t)t * 2 * BIMG + (size_t)n * KPIT + k;
    g_Bimg[base]        = hi;
    g_Bimg[base + BIMG] = lo;
}

// ---------------- fused conv1+gelu + warp-MMA conv2 -> fp16 table ----------------
__global__ __launch_bounds__(NTHR, 2)
void conv_tc(const float* __restrict__ input,
             const float* __restrict__ w1,
             const float* __restrict__ b1,
             const float* __restrict__ b2) {
    extern __shared__ char smem[];
    const uint32_t sb = smem_u32(smem);
    float* x_s = (float*)(smem + SM_X);
    float* w1s = (float*)(smem + SM_W1);
    float* b1s = (float*)(smem + SM_B1);
    float* b2s = (float*)(smem + SM_B2);

    const int tid  = threadIdx.x;
    const int wid  = tid >> 5;
    const int lane = tid & 31;
    const int blk  = blockIdx.x;
    const int tile = blk & 3;
    const int bv   = blk >> 2;
    const int b    = bv / NV;
    const int v    = bv - b * NV;
    const int d0   = tile * MT;

    // ---- stage x halo, conv1 weights, biases ----
    for (int i = tid; i < 8 * XP; i += NTHR) {
        int ci = i / XP, j = i - ci * XP;
        int dG = d0 - 2 + j;
        float val = 0.f;
        if ((unsigned)dG < (unsigned)ND)
            val = input[(((size_t)(b * NC + ci) * NV + v) * ND) + dG];
        x_s[i] = val;
    }
    for (int i = tid; i < HID * 24; i += NTHR)
        w1s[(i / 24) * 25 + (i % 24)] = w1[i];
    for (int i = tid; i < HID; i += NTHR) b1s[i] = b1[i];
    for (int i = tid; i < OC; i += NTHR)  b2s[i] = b2[i];

    // ---- async prefetch B(t=0, split=0) (overlaps conv1) ----
    {
        const char* src = (const char*)g_Bimg;
        for (int i = tid; i < BCHUNK / 16; i += NTHR)
            CP16(sb + SM_BS + i * 16, src + i * 16);
        CPCOMMIT();
    }
    __syncthreads();

    // ---- conv1 + gelu -> H[dd][hc] fp16 ----
    for (int u = tid; u < 33 * HID; u += NTHR) {
        int hc  = u % HID;                // lanes -> consecutive hc
        int ch  = u / HID;
        int ddb = ch * 4;

        float a4[4] = {b1s[hc], b1s[hc], b1s[hc], b1s[hc]};
        const float* wr = w1s + hc * 25;
#pragma unroll
        for (int ci = 0; ci < 8; ++ci) {
            const float* xr = x_s + ci * XP + ddb;
            float4 xa = *(const float4*)xr;
            float2 xb = *(const float2*)(xr + 4);
            float w0 = wr[ci * 3 + 0], w1v = wr[ci * 3 + 1], w2v = wr[ci * 3 + 2];
            float xv[6] = {xa.x, xa.y, xa.z, xa.w, xb.x, xb.y};
#pragma unroll
            for (int q = 0; q < 4; ++q) {
                a4[q] = fmaf(xv[q + 0], w0, a4[q]);
                a4[q] = fmaf(xv[q + 1], w1v, a4[q]);
                a4[q] = fmaf(xv[q + 2], w2v, a4[q]);
            }
        }
#pragma unroll
        for (int q = 0; q < 4; ++q) {
            int dd = ddb + q;                 // dd in [0,132)
            int dG = d0 - 1 + dd;
            float s = 0.f;
            if ((unsigned)dG < (unsigned)ND) s = gelu_f(a4[q]);
            ((__half*)(smem + SM_HB))[(size_t)dd * KPIT + hc] = __float2half_rn(s);
        }
    }
    CPWAIT0();
    __syncthreads();   // H + B(0,0) ready

    // ---- warp MMA: 4x3 warp grid, warp tile 32m x 32n ----
    const int m0 = (wid & 3) * 32;
    const int n0 = (wid >> 2) * 32;

    float acc[2][4][4];
#pragma unroll
    for (int i = 0; i < 2; ++i)
#pragma unroll
        for (int j = 0; j < 4; ++j)
#pragma unroll
            for (int q = 0; q < 4; ++q) acc[i][j][q] = 0.f;

    const uint32_t aRel = ((uint32_t)(m0 + (lane & 15)) * KPIT +
                           (uint32_t)(lane >> 4) * 8) * 2;
    const int g = lane >> 3;
    const uint32_t bRel = ((uint32_t)(n0 + (g >> 1) * 8 + (lane & 7)) * KPIT +
                           (uint32_t)(g & 1) * 8) * 2;
    const uint32_t ROWB = KPIT * 2;        // 368 bytes

#pragma unroll 1
    for (int it = 0; it < 6; ++it) {       // it = t*2 + split
        const int t = it >> 1;

        uint32_t aA = sb + SM_HB + aRel + (uint32_t)t * ROWB;
        uint32_t bB = sb + SM_BS + bRel;

#pragma unroll 1
        for (int ks = 0; ks < 11; ++ks) {
            uint32_t ah0[4], ah1[4];
            LDM4(ah0, aA);
            LDM4(ah1, aA + 16 * ROWB);
            uint32_t bb[2][4];
            LDM4(bb[0], bB);
            LDM4(bb[1], bB + 16 * ROWB);

#pragma unroll
            for (int j = 0; j < 4; ++j) {
                const int jj = j >> 1, pp = (j & 1) * 2;
                MMA(acc[0][j], ah0, bb[jj][pp], bb[jj][pp + 1]);
                MMA(acc[1][j], ah1, bb[jj][pp], bb[jj][pp + 1]);
            }
            aA += 32; bB += 32;
        }

        if (it < 5) {
            __syncthreads();   // B buffer free
            const char* src = (const char*)g_Bimg + (size_t)(it + 1) * BCHUNK;
            for (int i = tid; i < BCHUNK / 16; i += NTHR)
                CP16(sb + SM_BS + i * 16, src + i * 16);
            CPCOMMIT();
            CPWAIT0();
            __syncthreads();
        }
    }
    __syncthreads();   // all H reads done; reuse region for y staging

    // ---- epilogue: acc + bias -> fp16, permute oc -> (rr*8+ci) ----
    __half* y_s = (__half*)(smem + SM_HB);   // [128][96] halves
    const int rbase = (lane >> 2);
    const int cbase = (lane & 3) * 2;
#pragma unroll
    for (int i = 0; i < 2; ++i) {
#pragma unroll
        for (int j = 0; j < 4; ++j) {
            int col0 = n0 + j * 8 + cbase;
#pragma unroll
            for (int rh2 = 0; rh2 < 2; ++rh2) {
                int row = m0 + i * 16 + rbase + rh2 * 8;
#pragma unroll
                for (int ch2 = 0; ch2 < 2; ++ch2) {
                    int col = col0 + ch2;
                    if (col < OC) {
                        int ci = col / RR, rm = col - ci * RR;
                        y_s[(size_t)row * 96 + rm * 8 + ci] =
                            __float2half_rn(acc[i][j][rh2 * 2 + ch2] + b2s[col]);
                    }
                }
            }
        }
    }
    __syncthreads();

    // coalesced global write: g_Ah[(b*NP + v*512 + d0 + m)*88 + (r*8+c)]
    size_t gbase = ((size_t)b * NP + (size_t)v * ND + d0) * OC;
    for (int i = tid; i < MT * (OC / 2); i += NTHR) {
        int od = i / (OC / 2);
        int cu = i - od * (OC / 2);
        ((uint32_t*)(g_Ah + gbase + (size_t)od * OC))[cu] =
            ((const uint32_t*)(y_s + (size_t)od * 96))[cu];
    }
}

// ---------------- gather / interpolation (fp16 table, streaming stores) ----------------
__device__ __forceinline__ void stg_cs(float* p, float v) {
    asm volatile("st.global.cs.f32 [%0], %1;" :: "l"(p), "f"(v));
}

__global__ __launch_bounds__(256)
void gather_kernel(const float* __restrict__ idxs, float* __restrict__ out) {
    int j = blockIdx.x * 256 + threadIdx.x;
    if (j >= NIDX) return;

    float t  = idxs[j];
    float il = floorf(t);
    float w  = t - il;
    float w5 = w * 5.0f;
    float fw = floorf(w5);
    float lw = w5 - fw;

    int li = (int)(il * 11.0f + 5.0f + fw);
    int hi = li + 6;
    if (hi >= LL - 1) hi = LL - 2;

    float omlw = 1.0f - lw;
    float omw  = 1.0f - w;

#pragma unroll
    for (int b = 0; b < 2; ++b) {
        const __half* Ab = g_Ah + (size_t)b * (size_t)LL * 8u;
        uint4 va = __ldg((const uint4*)(Ab + (size_t)li * 8u));
        uint4 vb = __ldg((const uint4*)(Ab + (size_t)(li + 1) * 8u));
        uint4 ua = __ldg((const uint4*)(Ab + (size_t)hi * 8u));
        uint4 ub = __ldg((const uint4*)(Ab + (size_t)(hi + 1) * 8u));

        size_t obase = (size_t)b * 8u * (size_t)NIDX + (size_t)j;
#pragma unroll
        for (int p = 0; p < 4; ++p) {
            float2 a0 = __half22float2(((const __half2*)&va)[p]);
            float2 a1 = __half22float2(((const __half2*)&vb)[p]);
            float2 c0 = __half22float2(((const __half2*)&ua)[p]);
            float2 c1 = __half22float2(((const __half2*)&ub)[p]);

            float lowx  = a0.x * omlw + a1.x * lw;
            float lowy  = a0.y * omlw + a1.y * lw;
            float highx = c0.x * omlw + c1.x * lw;
            float highy = c0.y * omlw + c1.y * lw;

            stg_cs(out + obase + (size_t)(2 * p + 0) * NIDX, lowx * omw + highx * w);
            stg_cs(out + obase + (size_t)(2 * p + 1) * NIDX, lowy * omw + highy * w);
        }
    }
}

// ---------------- launch ----------------
extern "C" void kernel_launch(void* const* d_in, const int* in_sizes, int n_in,
                              void* d_out, int out_size) {
    const float* input = (const float*)d_in[0];
    const float* idxs  = (const float*)d_in[1];
    const float* fc1w  = (const float*)d_in[2];
    const float* fc1b  = (const float*)d_in[3];
    const float* fc2w  = (const float*)d_in[4];
    const float* fc2b  = (const float*)d_in[5];
    float* out = (float*)d_out;

    cudaFuncSetAttribute(conv_tc, cudaFuncAttributeMaxDynamicSharedMemorySize,
                         SM_TOT);

    prep_B<<<(3 * BIMG + 255) / 256, 256>>>(fc2w);
    conv_tc<<<NB * NV * (ND / MT), NTHR, SM_TOT>>>(input, fc1w, fc1b, fc2b);
    gather_kernel<<<NIDX / 256, 256>>>(idxs, out);
}

// round 10
// speedup vs baseline: 4.2434x; 1.1647x over previous
#include <cuda_runtime.h>
#include <cuda_bf16.h>
#include <cuda_fp16.h>
#include <math.h>
#include <stdint.h>

// ---------------- geometry ----------------
#define NB     2
#define NC     8
#define NV     360
#define ND     512
#define RR     11
#define HID    176
#define OC     88
#define NP     (NV*ND)
#define LL     (NP*RR)
#define NIDX   (128*128*360)

#define MT     128          // d positions per block
#define KPIT   184          // fp16 col pitch (368B rows -> conflict-free ldmatrix)
#define XP     136          // x_s pitch (floats)
#define NTHR   384          // 12 warps

// SMEM byte offsets
#define SM_X     0          // 8*136*4      = 4352
#define SM_W1    4352       // 176*25*4     = 17600
#define SM_B1    21952      // 176*4        = 704
#define SM_B2    22656      // 88*4 pad     = 384
#define SM_HB    23040      // 132*184*2    = 48576   (H fp16)
#define SM_BS    71616      // 96*184*2     = 35328   (one B tap)
#define SM_TOT   106944

#define BIMG    (96 * KPIT)             // 17664 halves per tap
#define BCHUNK  (BIMG * 2)              // 35328 bytes

// scratch (no cudaMalloc allowed)
__device__ __half g_Ah[2u * (unsigned)LL * 8u];          // fp16 table ~65MB
__device__ __align__(16) __half g_Bimg[3 * BIMG];        // [t][96*184] (hi only)

// ---------------- helpers ----------------
__device__ __forceinline__ uint32_t smem_u32(const void* p) {
    uint32_t a;
    asm("{ .reg .u64 t; cvta.to.shared.u64 t, %1; cvt.u32.u64 %0, t; }"
        : "=r"(a) : "l"(p));
    return a;
}

#define LDM4(d, addr)                                                        \
    asm volatile("ldmatrix.sync.aligned.m8n8.x4.shared.b16 "                 \
                 "{%0,%1,%2,%3}, [%4];"                                      \
                 : "=r"((d)[0]), "=r"((d)[1]), "=r"((d)[2]), "=r"((d)[3])    \
                 : "r"(addr) : "memory")

#define MMA(c, a, b0, b1)                                                    \
    asm volatile("mma.sync.aligned.m16n8k16.row.col.f32.f16.f16.f32 "        \
                 "{%0,%1,%2,%3},{%4,%5,%6,%7},{%8,%9},{%0,%1,%2,%3};"        \
                 : "+f"((c)[0]), "+f"((c)[1]), "+f"((c)[2]), "+f"((c)[3])    \
                 : "r"((a)[0]), "r"((a)[1]), "r"((a)[2]), "r"((a)[3]),       \
                   "r"(b0), "r"(b1))

#define CP16(dst, src)                                                       \
    asm volatile("cp.async.cg.shared.global [%0], [%1], 16;"                 \
                 :: "r"(dst), "l"(src) : "memory")
#define CPCOMMIT() asm volatile("cp.async.commit_group;" ::: "memory")
#define CPWAIT0()  asm volatile("cp.async.wait_group 0;"  ::: "memory")

// exact-accuracy cheap gelu: erf via A&S 7.1.26 (|eps| <= 1.5e-7)
__device__ __forceinline__ float gelu_f(float x) {
    float z = x * 0.70710678118654752f;
    float a = fabsf(z);
    float t = __fdividef(1.0f, fmaf(0.3275911f, a, 1.0f));
    float p = t * fmaf(t, fmaf(t, fmaf(t, fmaf(t, 1.061405429f, -1.453152027f),
                                       1.421413741f), -0.284496736f),
                       0.254829592f);
    float e = __expf(-a * a);
    float erfa = fmaf(-p, e, 1.0f);
    float erfz = copysignf(erfa, z);
    return 0.5f * x * (1.0f + erfz);
}

// ---- prep: fc2_w [88][176][3] -> per-tap contiguous fp16 images ----
__global__ void prep_B(const float* __restrict__ w2) {
    int i = blockIdx.x * 256 + threadIdx.x;     // over 3*96*184
    if (i >= 3 * BIMG) return;
    int k = i % KPIT;
    int n = (i / KPIT) % 96;
    int t = i / BIMG;
    float v = 0.f;
    if (n < OC && k < HID) v = w2[((size_t)n * HID + k) * 3 + t];
    g_Bimg[(size_t)t * BIMG + (size_t)n * KPIT + k] = __float2half_rn(v);
}

// ---------------- fused conv1+gelu + warp-MMA conv2 -> fp16 table ----------------
__global__ __launch_bounds__(NTHR, 2)
void conv_tc(const float* __restrict__ input,
             const float* __restrict__ w1,
             const float* __restrict__ b1,
             const float* __restrict__ b2) {
    extern __shared__ char smem[];
    const uint32_t sb = smem_u32(smem);
    float* x_s = (float*)(smem + SM_X);
    float* w1s = (float*)(smem + SM_W1);
    float* b1s = (float*)(smem + SM_B1);
    float* b2s = (float*)(smem + SM_B2);

    const int tid  = threadIdx.x;
    const int wid  = tid >> 5;
    const int lane = tid & 31;
    const int blk  = blockIdx.x;
    const int tile = blk & 3;
    const int bv   = blk >> 2;
    const int b    = bv / NV;
    const int v    = bv - b * NV;
    const int d0   = tile * MT;

    // ---- stage x halo, conv1 weights, biases ----
    for (int i = tid; i < 8 * XP; i += NTHR) {
        int ci = i / XP, j = i - ci * XP;
        int dG = d0 - 2 + j;
        float val = 0.f;
        if ((unsigned)dG < (unsigned)ND)
            val = input[(((size_t)(b * NC + ci) * NV + v) * ND) + dG];
        x_s[i] = val;
    }
    for (int i = tid; i < HID * 24; i += NTHR)
        w1s[(i / 24) * 25 + (i % 24)] = w1[i];
    for (int i = tid; i < HID; i += NTHR) b1s[i] = b1[i];
    for (int i = tid; i < OC; i += NTHR)  b2s[i] = b2[i];

    // ---- async prefetch B tap 0 (overlaps conv1) ----
    {
        const char* src = (const char*)g_Bimg;
        for (int i = tid; i < BCHUNK / 16; i += NTHR)
            CP16(sb + SM_BS + i * 16, src + i * 16);
        CPCOMMIT();
    }
    __syncthreads();

    // ---- conv1 + gelu -> H[dd][hc] fp16 ----
    for (int u = tid; u < 33 * HID; u += NTHR) {
        int hc  = u % HID;                // lanes -> consecutive hc
        int ch  = u / HID;
        int ddb = ch * 4;

        float a4[4] = {b1s[hc], b1s[hc], b1s[hc], b1s[hc]};
        const float* wr = w1s + hc * 25;
#pragma unroll
        for (int ci = 0; ci < 8; ++ci) {
            const float* xr = x_s + ci * XP + ddb;
            float4 xa = *(const float4*)xr;
            float2 xb = *(const float2*)(xr + 4);
            float w0 = wr[ci * 3 + 0], w1v = wr[ci * 3 + 1], w2v = wr[ci * 3 + 2];
            float xv[6] = {xa.x, xa.y, xa.z, xa.w, xb.x, xb.y};
#pragma unroll
            for (int q = 0; q < 4; ++q) {
                a4[q] = fmaf(xv[q + 0], w0, a4[q]);
                a4[q] = fmaf(xv[q + 1], w1v, a4[q]);
                a4[q] = fmaf(xv[q + 2], w2v, a4[q]);
            }
        }
#pragma unroll
        for (int q = 0; q < 4; ++q) {
            int dd = ddb + q;                 // dd in [0,132)
            int dG = d0 - 1 + dd;
            float s = 0.f;
            if ((unsigned)dG < (unsigned)ND) s = gelu_f(a4[q]);
            ((__half*)(smem + SM_HB))[(size_t)dd * KPIT + hc] = __float2half_rn(s);
        }
    }
    CPWAIT0();
    __syncthreads();   // H + B(0) ready

    // ---- warp MMA: 4x3 warp grid, warp tile 32m x 32n ----
    const int m0 = (wid & 3) * 32;
    const int n0 = (wid >> 2) * 32;

    float acc[2][4][4];
#pragma unroll
    for (int i = 0; i < 2; ++i)
#pragma unroll
        for (int j = 0; j < 4; ++j)
#pragma unroll
            for (int q = 0; q < 4; ++q) acc[i][j][q] = 0.f;

    const uint32_t aRel = ((uint32_t)(m0 + (lane & 15)) * KPIT +
                           (uint32_t)(lane >> 4) * 8) * 2;
    const int g = lane >> 3;
    const uint32_t bRel = ((uint32_t)(n0 + (g >> 1) * 8 + (lane & 7)) * KPIT +
                           (uint32_t)(g & 1) * 8) * 2;
    const uint32_t ROWB = KPIT * 2;        // 368 bytes

#pragma unroll 1
    for (int t = 0; t < 3; ++t) {
        uint32_t aA = sb + SM_HB + aRel + (uint32_t)t * ROWB;
        uint32_t bB = sb + SM_BS + bRel;

#pragma unroll 1
        for (int ks = 0; ks < 11; ++ks) {
            uint32_t ah0[4], ah1[4];
            LDM4(ah0, aA);
            LDM4(ah1, aA + 16 * ROWB);
            uint32_t bb[2][4];
            LDM4(bb[0], bB);
            LDM4(bb[1], bB + 16 * ROWB);

#pragma unroll
            for (int j = 0; j < 4; ++j) {
                const int jj = j >> 1, pp = (j & 1) * 2;
                MMA(acc[0][j], ah0, bb[jj][pp], bb[jj][pp + 1]);
                MMA(acc[1][j], ah1, bb[jj][pp], bb[jj][pp + 1]);
            }
            aA += 32; bB += 32;
        }

        if (t < 2) {
            __syncthreads();   // B buffer free
            const char* src = (const char*)g_Bimg + (size_t)(t + 1) * BCHUNK;
            for (int i = tid; i < BCHUNK / 16; i += NTHR)
                CP16(sb + SM_BS + i * 16, src + i * 16);
            CPCOMMIT();
            CPWAIT0();
            __syncthreads();
        }
    }
    __syncthreads();   // all H reads done; reuse region for y staging

    // ---- epilogue: acc + bias -> fp16, permute oc -> (rr*8+ci) ----
    __half* y_s = (__half*)(smem + SM_HB);   // [128][96] halves
    const int rbase = (lane >> 2);
    const int cbase = (lane & 3) * 2;
#pragma unroll
    for (int i = 0; i < 2; ++i) {
#pragma unroll
        for (int j = 0; j < 4; ++j) {
            int col0 = n0 + j * 8 + cbase;
#pragma unroll
            for (int rh2 = 0; rh2 < 2; ++rh2) {
                int row = m0 + i * 16 + rbase + rh2 * 8;
#pragma unroll
                for (int ch2 = 0; ch2 < 2; ++ch2) {
                    int col = col0 + ch2;
                    if (col < OC) {
                        int ci = col / RR, rm = col - ci * RR;
                        y_s[(size_t)row * 96 + rm * 8 + ci] =
                            __float2half_rn(acc[i][j][rh2 * 2 + ch2] + b2s[col]);
                    }
                }
            }
        }
    }
    __syncthreads();

    // coalesced global write: g_Ah[(b*NP + v*512 + d0 + m)*88 + (r*8+c)]
    size_t gbase = ((size_t)b * NP + (size_t)v * ND + d0) * OC;
    for (int i = tid; i < MT * (OC / 2); i += NTHR) {
        int od = i / (OC / 2);
        int cu = i - od * (OC / 2);
        ((uint32_t*)(g_Ah + gbase + (size_t)od * OC))[cu] =
            ((const uint32_t*)(y_s + (size_t)od * 96))[cu];
    }
}

// ---------------- gather / interpolation (fp16 table, streaming stores) ----------------
__device__ __forceinline__ void stg_cs(float* p, float v) {
    asm volatile("st.global.cs.f32 [%0], %1;" :: "l"(p), "f"(v));
}

__global__ __launch_bounds__(256)
void gather_kernel(const float* __restrict__ idxs, float* __restrict__ out) {
    int j = blockIdx.x * 256 + threadIdx.x;
    if (j >= NIDX) return;

    float t  = idxs[j];
    float il = floorf(t);
    float w  = t - il;
    float w5 = w * 5.0f;
    float fw = floorf(w5);
    float lw = w5 - fw;

    int li = (int)(il * 11.0f + 5.0f + fw);
    int hi = li + 6;
    if (hi >= LL - 1) hi = LL - 2;

    float omlw = 1.0f - lw;
    float omw  = 1.0f - w;

#pragma unroll
    for (int b = 0; b < 2; ++b) {
        const __half* Ab = g_Ah + (size_t)b * (size_t)LL * 8u;
        uint4 va = __ldg((const uint4*)(Ab + (size_t)li * 8u));
        uint4 vb = __ldg((const uint4*)(Ab + (size_t)(li + 1) * 8u));
        uint4 ua = __ldg((const uint4*)(Ab + (size_t)hi * 8u));
        uint4 ub = __ldg((const uint4*)(Ab + (size_t)(hi + 1) * 8u));

        size_t obase = (size_t)b * 8u * (size_t)NIDX + (size_t)j;
#pragma unroll
        for (int p = 0; p < 4; ++p) {
            float2 a0 = __half22float2(((const __half2*)&va)[p]);
            float2 a1 = __half22float2(((const __half2*)&vb)[p]);
            float2 c0 = __half22float2(((const __half2*)&ua)[p]);
            float2 c1 = __half22float2(((const __half2*)&ub)[p]);

            float lowx  = a0.x * omlw + a1.x * lw;
            float lowy  = a0.y * omlw + a1.y * lw;
            float highx = c0.x * omlw + c1.x * lw;
            float highy = c0.y * omlw + c1.y * lw;

            stg_cs(out + obase + (size_t)(2 * p + 0) * NIDX, lowx * omw + highx * w);
            stg_cs(out + obase + (size_t)(2 * p + 1) * NIDX, lowy * omw + highy * w);
        }
    }
}

// ---------------- launch ----------------
extern "C" void kernel_launch(void* const* d_in, const int* in_sizes, int n_in,
                              void* d_out, int out_size) {
    const float* input = (const float*)d_in[0];
    const float* idxs  = (const float*)d_in[1];
    const float* fc1w  = (const float*)d_in[2];
    const float* fc1b  = (const float*)d_in[3];
    const float* fc2w  = (const float*)d_in[4];
    const float* fc2b  = (const float*)d_in[5];
    float* out = (float*)d_out;

    cudaFuncSetAttribute(conv_tc, cudaFuncAttributeMaxDynamicSharedMemorySize,
                         SM_TOT);

    prep_B<<<(3 * BIMG + 255) / 256, 256>>>(fc2w);
    conv_tc<<<NB * NV * (ND / MT), NTHR, SM_TOT>>>(input, fc1w, fc1b, fc2b);
    gather_kernel<<<NIDX / 256, 256>>>(idxs, out);
}